// round 6
// baseline (speedup 1.0000x reference)
#include <cuda_runtime.h>
#include <math.h>

#define N_NODES 20000
#define E_EDGES 320000
#define ET      (E_EDGES + N_NODES)   /* 340000 with self loops */
#define MIDC    128
#define H01     4

/* ---------------- scratch (static device globals; no runtime alloc) -------- */
__device__ float g_H[N_NODES * 512];     // per-head features h[n][head][c]
__device__ float g_HOUT[N_NODES * 512];  // aggregated per-head output
__device__ float g_X[N_NODES * MIDC];    // current layer input features
__device__ float g_S[N_NODES * H01];     // src attention scores
__device__ float g_D[N_NODES * H01];     // dst attention scores
__device__ int   g_cnt[N_NODES];
__device__ int   g_rowptr[N_NODES + 1];
__device__ int   g_next[N_NODES];
__device__ int   g_col[ET];
__device__ float g_h2[N_NODES * 3];
__device__ float g_S2[N_NODES];
__device__ float g_D2[N_NODES];

/* ---------------- CSR build ------------------------------------------------ */
__global__ void k_zero_cnt() {
    int i = blockIdx.x * blockDim.x + threadIdx.x;
    if (i < N_NODES) g_cnt[i] = 0;
}

__global__ void k_count(const int* __restrict__ ei) {
    int e = blockIdx.x * blockDim.x + threadIdx.x;
    if (e >= ET) return;
    int dst = (e < E_EDGES) ? ei[E_EDGES + e] : (e - E_EDGES);
    atomicAdd(&g_cnt[dst], 1);
}

__global__ void k_scan() {
    __shared__ int s[1024];
    const int IT = (N_NODES + 1023) / 1024;  // 20
    int t = threadIdx.x;
    int base = t * IT;
    int sum = 0;
    for (int i = 0; i < IT; i++) {
        int idx = base + i;
        if (idx < N_NODES) sum += g_cnt[idx];
    }
    s[t] = sum;
    __syncthreads();
    for (int off = 1; off < 1024; off <<= 1) {
        int v = (t >= off) ? s[t - off] : 0;
        __syncthreads();
        s[t] += v;
        __syncthreads();
    }
    int run = s[t] - sum;  // exclusive prefix
    for (int i = 0; i < IT; i++) {
        int idx = base + i;
        if (idx < N_NODES) {
            g_rowptr[idx] = run;
            g_next[idx]   = run;
            run += g_cnt[idx];
        }
    }
    if (t == 1023) g_rowptr[N_NODES] = s[1023];
}

__global__ void k_scatter(const int* __restrict__ ei) {
    int e = blockIdx.x * blockDim.x + threadIdx.x;
    if (e >= ET) return;
    int src, dst;
    if (e < E_EDGES) { src = ei[e]; dst = ei[E_EDGES + e]; }
    else             { src = dst = e - E_EDGES; }
    int pos = atomicAdd(&g_next[dst], 1);
    g_col[pos] = src;
}

/* ---------------- layer 0 features (in=2) --------------------------------- */
__global__ void k_feat0(const float* __restrict__ x, const float* __restrict__ W0) {
    int idx = blockIdx.x * blockDim.x + threadIdx.x;  // N*512
    if (idx >= N_NODES * 512) return;
    int n = idx >> 9, j = idx & 511;
    g_H[idx] = W0[j * 2] * x[n * 2] + W0[j * 2 + 1] * x[n * 2 + 1];
}

/* ---------------- attention scores s/d for layers 0/1 ---------------------- */
__global__ void k_sd(const float* __restrict__ a_s, const float* __restrict__ a_d) {
    int gw   = (blockIdx.x * blockDim.x + threadIdx.x) >> 5;
    int lane = threadIdx.x & 31;
    if (gw >= N_NODES * H01) return;
    int n = gw >> 2, h = gw & 3;
    float4 hv = ((const float4*)&g_H[n * 512 + h * 128])[lane];
    float4 sa = ((const float4*)&a_s[h * 128])[lane];
    float4 da = ((const float4*)&a_d[h * 128])[lane];
    float ss = hv.x * sa.x + hv.y * sa.y + hv.z * sa.z + hv.w * sa.w;
    float dd = hv.x * da.x + hv.y * da.y + hv.z * da.z + hv.w * da.w;
    for (int o = 16; o; o >>= 1) {
        ss += __shfl_xor_sync(0xffffffffu, ss, o);
        dd += __shfl_xor_sync(0xffffffffu, dd, o);
    }
    if (!lane) { g_S[gw] = ss; g_D[gw] = dd; }
}

/* ---------------- layer 1 GEMM: g_X(N,128) @ W1(512,128)^T -> g_H(N,512) ---
 * NOTE: g_X is referenced INSIDE the kernel. Passing a __device__ symbol as a
 * host-side kernel argument takes the HOST shadow's address; on GB300
 * (pageableMemoryAccess=1 / ATS) that silently reads zero-filled host BSS
 * over NVLink-C2C instead of faulting. That was the round-1..3 bug.        */
#define BM 64
#define BN 64
#define BK 16
__global__ void k_gemm1(const float* __restrict__ W) {
    __shared__ float As[BK][BM + 1];
    __shared__ float Bs[BK][BN + 1];
    int tx = threadIdx.x, ty = threadIdx.y;  // 16x16
    int tid = ty * 16 + tx;
    int bm = blockIdx.y * BM;
    int bn = blockIdx.x * BN;
    float acc[4][4] = {};
    for (int k0 = 0; k0 < 128; k0 += BK) {
#pragma unroll
        for (int i = 0; i < 4; i++) {
            int e = tid + i * 256;
            int m = e / BK, k = e % BK;
            int gm = bm + m;
            As[k][m] = (gm < N_NODES) ? g_X[gm * 128 + k0 + k] : 0.f;
        }
#pragma unroll
        for (int i = 0; i < 4; i++) {
            int e = tid + i * 256;
            int n = e / BK, k = e % BK;
            Bs[k][n] = W[(bn + n) * 128 + k0 + k];
        }
        __syncthreads();
#pragma unroll
        for (int k = 0; k < BK; k++) {
            float a[4], b[4];
#pragma unroll
            for (int i = 0; i < 4; i++) a[i] = As[k][ty * 4 + i];
#pragma unroll
            for (int i = 0; i < 4; i++) b[i] = Bs[k][tx * 4 + i];
#pragma unroll
            for (int i = 0; i < 4; i++)
#pragma unroll
                for (int j = 0; j < 4; j++) acc[i][j] += a[i] * b[j];
        }
        __syncthreads();
    }
    for (int i = 0; i < 4; i++) {
        int gm = bm + ty * 4 + i;
        if (gm < N_NODES)
            for (int j = 0; j < 4; j++)
                g_H[gm * 512 + bn + tx * 4 + j] = acc[i][j];
    }
}

/* ---------------- GAT aggregation, layers 0/1 (warp per (dst,head)) ------- */
__global__ void k_agg() {
    int gw   = (blockIdx.x * blockDim.x + threadIdx.x) >> 5;
    int lane = threadIdx.x & 31;
    if (gw >= N_NODES * H01) return;
    int n = gw >> 2, h = gw & 3;
    int start = g_rowptr[n], end = g_rowptr[n + 1];
    float dn = g_D[n * H01 + h];

    float m = -1e30f;
    for (int e = start + lane; e < end; e += 32) {
        float l = g_S[g_col[e] * H01 + h] + dn;
        l = l >= 0.f ? l : 0.2f * l;
        m = fmaxf(m, l);
    }
    for (int o = 16; o; o >>= 1) m = fmaxf(m, __shfl_xor_sync(0xffffffffu, m, o));

    float sum = 0.f;
    for (int e = start + lane; e < end; e += 32) {
        float l = g_S[g_col[e] * H01 + h] + dn;
        l = l >= 0.f ? l : 0.2f * l;
        sum += __expf(l - m);
    }
    for (int o = 16; o; o >>= 1) sum += __shfl_xor_sync(0xffffffffu, sum, o);
    float inv = 1.f / (sum + 1e-16f);

    float4 acc = {0.f, 0.f, 0.f, 0.f};
    for (int e = start; e < end; e++) {
        int src = g_col[e];
        float l = g_S[src * H01 + h] + dn;       // broadcast load
        l = l >= 0.f ? l : 0.2f * l;
        float alpha = __expf(l - m) * inv;
        float4 hv = ((const float4*)&g_H[src * 512 + h * 128])[lane];
        acc.x += hv.x * alpha;
        acc.y += hv.y * alpha;
        acc.z += hv.z * alpha;
        acc.w += hv.w * alpha;
    }
    ((float4*)&g_HOUT[n * 512 + h * 128])[lane] = acc;
}

/* ---------------- head-mean + bias + ELU + BN ------------------------------ */
__global__ void k_post(const float* __restrict__ b, const float* __restrict__ g,
                       const float* __restrict__ bb, const float* __restrict__ mm,
                       const float* __restrict__ vv) {
    int idx = blockIdx.x * blockDim.x + threadIdx.x;
    if (idx >= N_NODES * MIDC) return;
    int n = idx >> 7, c = idx & 127;
    float v = 0.25f * (g_HOUT[n * 512 + c] + g_HOUT[n * 512 + 128 + c] +
                       g_HOUT[n * 512 + 256 + c] + g_HOUT[n * 512 + 384 + c]) + b[c];
    v = v > 0.f ? v : (expf(v) - 1.f);
    v = (v - mm[c]) * rsqrtf(vv[c] + 1e-5f) * g[c] + bb[c];
    g_X[idx] = v;
}

/* ---------------- layer 2 features (out=3, H=1) ---------------------------- */
__global__ void k_feat2(const float* __restrict__ W2) {
    int gw   = (blockIdx.x * blockDim.x + threadIdx.x) >> 5;
    int lane = threadIdx.x & 31;
    if (gw >= N_NODES * 3) return;
    int n = gw / 3, j = gw % 3;
    float4 xv = ((const float4*)&g_X[n * 128])[lane];
    float4 wv = ((const float4*)&W2[j * 128])[lane];
    float s = xv.x * wv.x + xv.y * wv.y + xv.z * wv.z + xv.w * wv.w;
    for (int o = 16; o; o >>= 1) s += __shfl_xor_sync(0xffffffffu, s, o);
    if (!lane) g_h2[n * 3 + j] = s;
}

__global__ void k_sd2(const float* __restrict__ as2, const float* __restrict__ ad2) {
    int n = blockIdx.x * blockDim.x + threadIdx.x;
    if (n >= N_NODES) return;
    float h0 = g_h2[n * 3], h1 = g_h2[n * 3 + 1], h2v = g_h2[n * 3 + 2];
    g_S2[n] = h0 * as2[0] + h1 * as2[1] + h2v * as2[2];
    g_D2[n] = h0 * ad2[0] + h1 * ad2[1] + h2v * ad2[2];
}

/* ---------------- layer 2 aggregation + velocity ODE ----------------------- */
__global__ void k_final(const float* __restrict__ b2, const float* __restrict__ kk,
                        const float* __restrict__ dd, const float* __restrict__ t0p,
                        const float* __restrict__ u0p, const float* __restrict__ t,
                        float* __restrict__ out) {
    int n = blockIdx.x * blockDim.x + threadIdx.x;
    if (n >= N_NODES) return;
    int start = g_rowptr[n], end = g_rowptr[n + 1];
    float dn = g_D2[n];

    float m = -1e30f;
    for (int e = start; e < end; e++) {
        float l = g_S2[g_col[e]] + dn;
        l = l >= 0.f ? l : 0.2f * l;
        m = fmaxf(m, l);
    }
    float sum = 0.f;
    for (int e = start; e < end; e++) {
        float l = g_S2[g_col[e]] + dn;
        l = l >= 0.f ? l : 0.2f * l;
        sum += expf(l - m);
    }
    float inv = 1.f / (sum + 1e-16f);
    float a0 = 0.f, a1 = 0.f, a2 = 0.f;
    for (int e = start; e < end; e++) {
        int src = g_col[e];
        float l = g_S2[src] + dn;
        l = l >= 0.f ? l : 0.2f * l;
        float alpha = expf(l - m) * inv;
        a0 += g_h2[src * 3] * alpha;
        a1 += g_h2[src * 3 + 1] * alpha;
        a2 += g_h2[src * 3 + 2] * alpha;
    }
    float ar  = a0 + b2[0]; ar  = ar  > 0.f ? ar  : (expf(ar)  - 1.f);
    float gam = a1 + b2[1]; gam = gam > 0.f ? gam : (expf(gam) - 1.f);
    float bet = a2 + b2[2]; bet = bet > 0.f ? bet : (expf(bet) - 1.f);

    float tt = t[n];
    float K = kk[0], D = dd[0], T0 = t0p[0], U0 = u0p[0];
    float S = 1.f / (1.f + expf(-K * (tt - T0 - D)));
    float eb  = expf(-bet * tt);
    float eg  = expf(-gam * tt);
    float ebs = expf(-bet * (tt - T0));
    float egs = expf(-gam * (tt - T0));
    float ab = ar / bet;
    float ag = ar / gam;
    float tu = ab * (1.f - eb) * (1.f - S) + ab * S + (U0 * ebs - ab) * S;
    float inv_gb = 1.f / (gam - bet);
    float ts = (ag * (1.f - eg) + ar * inv_gb * (eg - eb)) * (1.f - S)
             + ag * S + bet * U0 * inv_gb * (egs - ebs) * S;

    out[n]           = tu;
    out[N_NODES + n] = ts;
}

/* ---------------- launcher ------------------------------------------------- */
extern "C" void kernel_launch(void* const* d_in, const int* in_sizes, int n_in,
                              void* d_out, int out_size) {
    const float* x   = (const float*)d_in[0];
    const int*   ei  = (const int*)  d_in[1];
    const float* W0  = (const float*)d_in[3];
    const float* as0 = (const float*)d_in[4];
    const float* ad0 = (const float*)d_in[5];
    const float* b0  = (const float*)d_in[6];
    const float* W1  = (const float*)d_in[7];
    const float* as1 = (const float*)d_in[8];
    const float* ad1 = (const float*)d_in[9];
    const float* b1  = (const float*)d_in[10];
    const float* W2  = (const float*)d_in[11];
    const float* as2 = (const float*)d_in[12];
    const float* ad2 = (const float*)d_in[13];
    const float* b2  = (const float*)d_in[14];
    const float* bng0 = (const float*)d_in[15];
    const float* bnb0 = (const float*)d_in[16];
    const float* bnm0 = (const float*)d_in[17];
    const float* bnv0 = (const float*)d_in[18];
    const float* bng1 = (const float*)d_in[19];
    const float* bnb1 = (const float*)d_in[20];
    const float* bnm1 = (const float*)d_in[21];
    const float* bnv1 = (const float*)d_in[22];
    const float* kk  = (const float*)d_in[23];
    const float* dd  = (const float*)d_in[24];
    const float* t0p = (const float*)d_in[25];
    const float* u0p = (const float*)d_in[26];
    const float* t   = (const float*)d_in[27];
    float* out = (float*)d_out;

    /* CSR build */
    k_zero_cnt<<<(N_NODES + 255) / 256, 256>>>();
    k_count<<<(ET + 255) / 256, 256>>>(ei);
    k_scan<<<1, 1024>>>();
    k_scatter<<<(ET + 255) / 256, 256>>>(ei);

    /* layer 0 */
    k_feat0<<<(N_NODES * 512 + 255) / 256, 256>>>(x, W0);
    k_sd<<<(N_NODES * H01 * 32 + 255) / 256, 256>>>(as0, ad0);
    k_agg<<<(N_NODES * H01 * 32 + 255) / 256, 256>>>();
    k_post<<<(N_NODES * MIDC + 255) / 256, 256>>>(b0, bng0, bnb0, bnm0, bnv0);

    /* layer 1 */
    {
        dim3 grid(512 / BN, (N_NODES + BM - 1) / BM);
        dim3 block(16, 16);
        k_gemm1<<<grid, block>>>(W1);
    }
    k_sd<<<(N_NODES * H01 * 32 + 255) / 256, 256>>>(as1, ad1);
    k_agg<<<(N_NODES * H01 * 32 + 255) / 256, 256>>>();
    k_post<<<(N_NODES * MIDC + 255) / 256, 256>>>(b1, bng1, bnb1, bnm1, bnv1);

    /* layer 2 + ODE */
    k_feat2<<<(N_NODES * 3 * 32 + 255) / 256, 256>>>(W2);
    k_sd2<<<(N_NODES + 255) / 256, 256>>>(as2, ad2);
    k_final<<<(N_NODES + 255) / 256, 256>>>(b2, kk, dd, t0p, u0p, t, out);
}

// round 7
// speedup vs baseline: 1.2461x; 1.2461x over previous
#include <cuda_runtime.h>
#include <math.h>

#define N_NODES 20000
#define E_EDGES 320000
#define ET      (E_EDGES + N_NODES)   /* 340000 with self loops */
#define MIDC    128
#define H01     4

/* ---------------- scratch (static device globals; no runtime alloc) -------- */
__device__ float g_H[N_NODES * 512];     // per-head features h[n][head][c]
__device__ float g_X[N_NODES * MIDC];    // current layer input features
__device__ float g_S[N_NODES * H01];     // src attention scores
__device__ float g_D[N_NODES * H01];     // dst attention scores
__device__ int   g_cnt[N_NODES];
__device__ int   g_rowptr[N_NODES + 1];
__device__ int   g_next[N_NODES];
__device__ int   g_col[ET];
__device__ float g_h2[N_NODES * 3];
__device__ float g_S2[N_NODES];
__device__ float g_D2[N_NODES];

/* ---------------- CSR build ------------------------------------------------ */
__global__ void k_zero_cnt() {
    int i = blockIdx.x * blockDim.x + threadIdx.x;
    if (i < N_NODES) g_cnt[i] = 1;           /* self-loop pre-counted */
}

__global__ void k_count(const int* __restrict__ ei) {
    int e = blockIdx.x * blockDim.x + threadIdx.x;
    if (e >= E_EDGES) return;
    atomicAdd(&g_cnt[ei[E_EDGES + e]], 1);
}

__global__ void k_scan() {
    __shared__ int s[1024];
    const int IT = (N_NODES + 1023) / 1024;  // 20
    int t = threadIdx.x;
    int base = t * IT;
    int sum = 0;
    for (int i = 0; i < IT; i++) {
        int idx = base + i;
        if (idx < N_NODES) sum += g_cnt[idx];
    }
    s[t] = sum;
    __syncthreads();
    for (int off = 1; off < 1024; off <<= 1) {
        int v = (t >= off) ? s[t - off] : 0;
        __syncthreads();
        s[t] += v;
        __syncthreads();
    }
    int run = s[t] - sum;  // exclusive prefix
    for (int i = 0; i < IT; i++) {
        int idx = base + i;
        if (idx < N_NODES) {
            g_rowptr[idx] = run;
            g_next[idx]   = run;
            run += g_cnt[idx];
        }
    }
    if (t == 1023) g_rowptr[N_NODES] = s[1023];
}

__global__ void k_scatter(const int* __restrict__ ei) {
    int e = blockIdx.x * blockDim.x + threadIdx.x;
    if (e >= ET) return;
    int src, dst;
    if (e < E_EDGES) { src = ei[e]; dst = ei[E_EDGES + e]; }
    else             { src = dst = e - E_EDGES; }
    int pos = atomicAdd(&g_next[dst], 1);
    g_col[pos] = src;
}

/* ---------------- layer 0: features (in=2) + attention scores, fused ------- */
__global__ void k_feat0sd(const float* __restrict__ x, const float* __restrict__ W0,
                          const float* __restrict__ a_s, const float* __restrict__ a_d) {
    int gw   = (blockIdx.x * blockDim.x + threadIdx.x) >> 5;
    int lane = threadIdx.x & 31;
    if (gw >= N_NODES * H01) return;
    int n = gw >> 2, h = gw & 3;
    float x0 = x[n * 2], x1 = x[n * 2 + 1];
    int j = h * 128 + lane * 4;              /* 4 output channels per lane */
    float4 w01 = ((const float4*)W0)[(j >> 1)];        /* rows j, j+1 */
    float4 w23 = ((const float4*)W0)[(j >> 1) + 1];    /* rows j+2, j+3 */
    float4 hv;
    hv.x = w01.x * x0 + w01.y * x1;
    hv.y = w01.z * x0 + w01.w * x1;
    hv.z = w23.x * x0 + w23.y * x1;
    hv.w = w23.z * x0 + w23.w * x1;
    ((float4*)&g_H[n * 512 + h * 128])[lane] = hv;
    float4 sa = ((const float4*)&a_s[h * 128])[lane];
    float4 da = ((const float4*)&a_d[h * 128])[lane];
    float ss = hv.x * sa.x + hv.y * sa.y + hv.z * sa.z + hv.w * sa.w;
    float dd = hv.x * da.x + hv.y * da.y + hv.z * da.z + hv.w * da.w;
    for (int o = 16; o; o >>= 1) {
        ss += __shfl_xor_sync(0xffffffffu, ss, o);
        dd += __shfl_xor_sync(0xffffffffu, dd, o);
    }
    if (!lane) { g_S[gw] = ss; g_D[gw] = dd; }
}

/* ---------------- layer 1 GEMM (128x128 tile, 8x8/thread) + fused scores ---
 * g_X(N,128) @ W1(512,128)^T -> g_H(N,512).  BN=128 => block cols == one head,
 * so the a_s/a_d dot products are computed in the epilogue (half-warp shfl). */
#define GBM 128
#define GBN 128
#define GBK 16
__global__ void __launch_bounds__(256) k_gemm_sd(const float* __restrict__ W,
                                                 const float* __restrict__ a_s,
                                                 const float* __restrict__ a_d) {
    __shared__ float As[GBK][GBM + 4];
    __shared__ float Bs[GBK][GBN + 4];
    int tid = threadIdx.x;
    int tx = tid & 15, ty = tid >> 4;        /* 16x16 threads */
    int bm = blockIdx.y * GBM;
    int bn = blockIdx.x * GBN;               /* head = blockIdx.x */
    float acc[8][8] = {};
    for (int k0 = 0; k0 < 128; k0 += GBK) {
#pragma unroll
        for (int i = 0; i < 2; i++) {
            int idx = tid + i * 256;         /* 512 float4 loads: m=idx/4, kg=idx%4 */
            int m = idx >> 2, kg = idx & 3;
            int gm = bm + m;
            float4 v = (gm < N_NODES)
                ? *(const float4*)&g_X[gm * 128 + k0 + kg * 4]
                : make_float4(0.f, 0.f, 0.f, 0.f);
            As[kg * 4 + 0][m] = v.x;
            As[kg * 4 + 1][m] = v.y;
            As[kg * 4 + 2][m] = v.z;
            As[kg * 4 + 3][m] = v.w;
            float4 w = *(const float4*)&W[(bn + m) * 128 + k0 + kg * 4];
            Bs[kg * 4 + 0][m] = w.x;
            Bs[kg * 4 + 1][m] = w.y;
            Bs[kg * 4 + 2][m] = w.z;
            Bs[kg * 4 + 3][m] = w.w;
        }
        __syncthreads();
#pragma unroll
        for (int k = 0; k < GBK; k++) {
            float a[8], b[8];
            *(float4*)&a[0] = *(float4*)&As[k][ty * 8];
            *(float4*)&a[4] = *(float4*)&As[k][ty * 8 + 4];
            *(float4*)&b[0] = *(float4*)&Bs[k][tx * 8];
            *(float4*)&b[4] = *(float4*)&Bs[k][tx * 8 + 4];
#pragma unroll
            for (int i = 0; i < 8; i++)
#pragma unroll
                for (int j = 0; j < 8; j++) acc[i][j] += a[i] * b[j];
        }
        __syncthreads();
    }
    /* store h tile */
#pragma unroll
    for (int i = 0; i < 8; i++) {
        int gm = bm + ty * 8 + i;
        if (gm < N_NODES) {
            *(float4*)&g_H[gm * 512 + bn + tx * 8]     = *(float4*)&acc[i][0];
            *(float4*)&g_H[gm * 512 + bn + tx * 8 + 4] = *(float4*)&acc[i][4];
        }
    }
    /* fused attention scores: head h = blockIdx.x, cols of this block = h*128.. */
    int h = blockIdx.x;
    float asv[8], adv[8];
#pragma unroll
    for (int j = 0; j < 8; j++) {
        asv[j] = a_s[h * 128 + tx * 8 + j];
        adv[j] = a_d[h * 128 + tx * 8 + j];
    }
    float ps[8], pd[8];
#pragma unroll
    for (int i = 0; i < 8; i++) {
        float s = 0.f, d = 0.f;
#pragma unroll
        for (int j = 0; j < 8; j++) { s += acc[i][j] * asv[j]; d += acc[i][j] * adv[j]; }
        ps[i] = s; pd[i] = d;
    }
    /* reduce over tx: the 16 tx values for a given ty are one half-warp */
#pragma unroll
    for (int o = 8; o; o >>= 1) {
#pragma unroll
        for (int i = 0; i < 8; i++) {
            ps[i] += __shfl_xor_sync(0xffffffffu, ps[i], o);
            pd[i] += __shfl_xor_sync(0xffffffffu, pd[i], o);
        }
    }
    if (tx == 0) {
#pragma unroll
        for (int i = 0; i < 8; i++) {
            int gm = bm + ty * 8 + i;
            if (gm < N_NODES) {
                g_S[gm * H01 + h] = ps[i];
                g_D[gm * H01 + h] = pd[i];
            }
        }
    }
}

/* ---------------- fused GAT aggregation + head-mean + ELU + BN -------------
 * One block (128 threads = 4 warps) per dst node; warp w handles head w.    */
__global__ void __launch_bounds__(128) k_agg_post(
        const float* __restrict__ b, const float* __restrict__ g,
        const float* __restrict__ bb, const float* __restrict__ mm,
        const float* __restrict__ vv) {
    __shared__ float s_h[4][128];
    int n = blockIdx.x;
    int h = threadIdx.x >> 5;
    int lane = threadIdx.x & 31;
    int start = g_rowptr[n], end = g_rowptr[n + 1];
    float dn = g_D[n * H01 + h];

    float m = -1e30f;
    for (int e = start + lane; e < end; e += 32) {
        float l = g_S[g_col[e] * H01 + h] + dn;
        l = l >= 0.f ? l : 0.2f * l;
        m = fmaxf(m, l);
    }
    for (int o = 16; o; o >>= 1) m = fmaxf(m, __shfl_xor_sync(0xffffffffu, m, o));

    float sum = 0.f;
    for (int e = start + lane; e < end; e += 32) {
        float l = g_S[g_col[e] * H01 + h] + dn;
        l = l >= 0.f ? l : 0.2f * l;
        sum += __expf(l - m);
    }
    for (int o = 16; o; o >>= 1) sum += __shfl_xor_sync(0xffffffffu, sum, o);
    float inv = 1.f / (sum + 1e-16f);

    float4 acc = {0.f, 0.f, 0.f, 0.f};
    for (int e = start; e < end; e++) {
        int src = g_col[e];
        float l = g_S[src * H01 + h] + dn;       /* broadcast load */
        l = l >= 0.f ? l : 0.2f * l;
        float alpha = __expf(l - m) * inv;
        float4 hv = ((const float4*)&g_H[src * 512 + h * 128])[lane];
        acc.x += hv.x * alpha;
        acc.y += hv.y * alpha;
        acc.z += hv.z * alpha;
        acc.w += hv.w * alpha;
    }
    ((float4*)&s_h[h][0])[lane] = acc;
    __syncthreads();

    /* head mean + bias + ELU + BN: thread t -> channel t */
    int c = threadIdx.x;
    float v = 0.25f * (s_h[0][c] + s_h[1][c] + s_h[2][c] + s_h[3][c]) + b[c];
    v = v > 0.f ? v : (expf(v) - 1.f);
    v = (v - mm[c]) * rsqrtf(vv[c] + 1e-5f) * g[c] + bb[c];
    g_X[n * 128 + c] = v;
}

/* ---------------- layer 2 features (out=3, H=1) ---------------------------- */
__global__ void k_feat2(const float* __restrict__ W2) {
    int gw   = (blockIdx.x * blockDim.x + threadIdx.x) >> 5;
    int lane = threadIdx.x & 31;
    if (gw >= N_NODES * 3) return;
    int n = gw / 3, j = gw % 3;
    float4 xv = ((const float4*)&g_X[n * 128])[lane];
    float4 wv = ((const float4*)&W2[j * 128])[lane];
    float s = xv.x * wv.x + xv.y * wv.y + xv.z * wv.z + xv.w * wv.w;
    for (int o = 16; o; o >>= 1) s += __shfl_xor_sync(0xffffffffu, s, o);
    if (!lane) g_h2[n * 3 + j] = s;
}

__global__ void k_sd2(const float* __restrict__ as2, const float* __restrict__ ad2) {
    int n = blockIdx.x * blockDim.x + threadIdx.x;
    if (n >= N_NODES) return;
    float h0 = g_h2[n * 3], h1 = g_h2[n * 3 + 1], h2v = g_h2[n * 3 + 2];
    g_S2[n] = h0 * as2[0] + h1 * as2[1] + h2v * as2[2];
    g_D2[n] = h0 * ad2[0] + h1 * ad2[1] + h2v * ad2[2];
}

/* ---------------- layer 2 aggregation + velocity ODE ----------------------- */
__global__ void k_final(const float* __restrict__ b2, const float* __restrict__ kk,
                        const float* __restrict__ dd, const float* __restrict__ t0p,
                        const float* __restrict__ u0p, const float* __restrict__ t,
                        float* __restrict__ out) {
    int n = blockIdx.x * blockDim.x + threadIdx.x;
    if (n >= N_NODES) return;
    int start = g_rowptr[n], end = g_rowptr[n + 1];
    float dn = g_D2[n];

    float m = -1e30f;
    for (int e = start; e < end; e++) {
        float l = g_S2[g_col[e]] + dn;
        l = l >= 0.f ? l : 0.2f * l;
        m = fmaxf(m, l);
    }
    float sum = 0.f;
    for (int e = start; e < end; e++) {
        float l = g_S2[g_col[e]] + dn;
        l = l >= 0.f ? l : 0.2f * l;
        sum += expf(l - m);
    }
    float inv = 1.f / (sum + 1e-16f);
    float a0 = 0.f, a1 = 0.f, a2 = 0.f;
    for (int e = start; e < end; e++) {
        int src = g_col[e];
        float l = g_S2[src] + dn;
        l = l >= 0.f ? l : 0.2f * l;
        float alpha = expf(l - m) * inv;
        a0 += g_h2[src * 3] * alpha;
        a1 += g_h2[src * 3 + 1] * alpha;
        a2 += g_h2[src * 3 + 2] * alpha;
    }
    float ar  = a0 + b2[0]; ar  = ar  > 0.f ? ar  : (expf(ar)  - 1.f);
    float gam = a1 + b2[1]; gam = gam > 0.f ? gam : (expf(gam) - 1.f);
    float bet = a2 + b2[2]; bet = bet > 0.f ? bet : (expf(bet) - 1.f);

    float tt = t[n];
    float K = kk[0], D = dd[0], T0 = t0p[0], U0 = u0p[0];
    float S = 1.f / (1.f + expf(-K * (tt - T0 - D)));
    float eb  = expf(-bet * tt);
    float eg  = expf(-gam * tt);
    float ebs = expf(-bet * (tt - T0));
    float egs = expf(-gam * (tt - T0));
    float ab = ar / bet;
    float ag = ar / gam;
    float tu = ab * (1.f - eb) * (1.f - S) + ab * S + (U0 * ebs - ab) * S;
    float inv_gb = 1.f / (gam - bet);
    float ts = (ag * (1.f - eg) + ar * inv_gb * (eg - eb)) * (1.f - S)
             + ag * S + bet * U0 * inv_gb * (egs - ebs) * S;

    out[n]           = tu;
    out[N_NODES + n] = ts;
}

/* ---------------- launcher ------------------------------------------------- */
extern "C" void kernel_launch(void* const* d_in, const int* in_sizes, int n_in,
                              void* d_out, int out_size) {
    const float* x   = (const float*)d_in[0];
    const int*   ei  = (const int*)  d_in[1];
    const float* W0  = (const float*)d_in[3];
    const float* as0 = (const float*)d_in[4];
    const float* ad0 = (const float*)d_in[5];
    const float* b0  = (const float*)d_in[6];
    const float* W1  = (const float*)d_in[7];
    const float* as1 = (const float*)d_in[8];
    const float* ad1 = (const float*)d_in[9];
    const float* b1  = (const float*)d_in[10];
    const float* W2  = (const float*)d_in[11];
    const float* as2 = (const float*)d_in[12];
    const float* ad2 = (const float*)d_in[13];
    const float* b2  = (const float*)d_in[14];
    const float* bng0 = (const float*)d_in[15];
    const float* bnb0 = (const float*)d_in[16];
    const float* bnm0 = (const float*)d_in[17];
    const float* bnv0 = (const float*)d_in[18];
    const float* bng1 = (const float*)d_in[19];
    const float* bnb1 = (const float*)d_in[20];
    const float* bnm1 = (const float*)d_in[21];
    const float* bnv1 = (const float*)d_in[22];
    const float* kk  = (const float*)d_in[23];
    const float* dd  = (const float*)d_in[24];
    const float* t0p = (const float*)d_in[25];
    const float* u0p = (const float*)d_in[26];
    const float* t   = (const float*)d_in[27];
    float* out = (float*)d_out;

    /* CSR build */
    k_zero_cnt<<<(N_NODES + 255) / 256, 256>>>();
    k_count<<<(E_EDGES + 255) / 256, 256>>>(ei);
    k_scan<<<1, 1024>>>();
    k_scatter<<<(ET + 255) / 256, 256>>>(ei);

    /* layer 0 */
    k_feat0sd<<<(N_NODES * H01 * 32 + 255) / 256, 256>>>(x, W0, as0, ad0);
    k_agg_post<<<N_NODES, 128>>>(b0, bng0, bnb0, bnm0, bnv0);

    /* layer 1 */
    {
        dim3 grid(512 / GBN, (N_NODES + GBM - 1) / GBM);
        k_gemm_sd<<<grid, 256>>>(W1, as1, ad1);
    }
    k_agg_post<<<N_NODES, 128>>>(b1, bng1, bnb1, bnm1, bnv1);

    /* layer 2 + ODE */
    k_feat2<<<(N_NODES * 3 * 32 + 255) / 256, 256>>>(W2);
    k_sd2<<<(N_NODES + 255) / 256, 256>>>(as2, ad2);
    k_final<<<(N_NODES + 255) / 256, 256>>>(b2, kk, dd, t0p, u0p, t, out);
}